// round 15
// baseline (speedup 1.0000x reference)
#include <cuda_runtime.h>
#include <cuda_fp16.h>
#include <cstdint>

#define C_IN 128
#define KOUT 256
#define NIMG 32
#define TIL  28                       // 28x28 tiles of 2x2 outputs
#define PT2  (NIMG*TIL*TIL)           // 25088 GEMM rows
#define VS2  ((size_t)PT2*C_IN)       // per-t V plane
#define NCH  32                       // 16 GEMMs x 2 ch-halves, K=64 each

// 2D-Winograd-transformed scratch
__device__ __align__(128) __half g_v[16 * VS2];              // [t=4i+j][p2][c]
__device__ __align__(128) __half g_u[16 * KOUT * C_IN];      // [t][k][c], i=3 negated

__constant__ int c_iord[4] = {1, 2, 0, 3};   // inner i processing order

__device__ __forceinline__ float quant16f(float v) {
    float r = rintf(v * 4096.0f);
    r = fminf(fmaxf(r, -32768.0f), 32767.0f);
    return r * (1.0f / 4096.0f);
}

__device__ __forceinline__ uint32_t su32(const void* p) {
    uint32_t a;
    asm("{ .reg .u64 t; cvta.to.shared.u64 t, %1; cvt.u32.u64 %0, t; }"
        : "=r"(a) : "l"(p));
    return a;
}

// ---------------- pre-kernels ----------------
// V: blocks [0,1792): b -> (th = b%28, cb = (b/28)&1 [64ch], n = b/56)
// U: blocks [1792, 1792+128)
#define NBLK_V 1792
#define PREP_SMEM (4 * 64 * 61 * 4)    // xs[(rr*64+c)*61 + col] floats

__global__ void prep_all(const float* __restrict__ x, const float* __restrict__ w) {
    const int b = blockIdx.x;
    const int tid = threadIdx.x;

    if (b >= NBLK_V) {
        // ---- U = G g G^T, i=3 planes negated ----
        int idx = (b - NBLK_V) * 256 + tid;
        int k = idx >> 7, c = idx & 127;
        const float* gp = w + (size_t)k * 1152 + c * 9;
        float g[3][3];
        #pragma unroll
        for (int r = 0; r < 3; r++)
            #pragma unroll
            for (int s = 0; s < 3; s++) g[r][s] = quant16f(gp[r * 3 + s]);
        float t2[4][3];
        #pragma unroll
        for (int s = 0; s < 3; s++) {
            t2[0][s] = g[0][s];
            t2[1][s] = 0.5f * (g[0][s] + g[1][s] + g[2][s]);
            t2[2][s] = 0.5f * (g[0][s] - g[1][s] + g[2][s]);
            t2[3][s] = g[2][s];
        }
        #pragma unroll
        for (int i = 0; i < 4; i++) {
            float sgn = (i == 3) ? -1.0f : 1.0f;
            float u[4];
            u[0] = t2[i][0];
            u[1] = 0.5f * (t2[i][0] + t2[i][1] + t2[i][2]);
            u[2] = 0.5f * (t2[i][0] - t2[i][1] + t2[i][2]);
            u[3] = t2[i][2];
            #pragma unroll
            for (int j = 0; j < 4; j++)
                g_u[((size_t)((i * 4 + j) * KOUT + k)) * C_IN + c] =
                    __float2half(sgn * u[j]);
        }
        return;
    }

    // ---- V = B^T d B: one (n, th, 64-channel block) ----
    extern __shared__ float xs[];      // [(rr*64 + c)*61 + col]
    const int th = b % TIL;
    const int cb = (b / TIL) & 1;
    const int n  = b / (TIL * 2);

    // coalesced load: i -> col = i&63 (<58), rr = (i>>6)&3, c = i>>8
    for (int i = tid; i < 64 * 4 * 64; i += 256) {
        const int col = i & 63;
        if (col >= 58) continue;
        const int rr = (i >> 6) & 3;
        const int c  = i >> 8;
        const int h  = 2 * th - 1 + rr;
        const int ww = col - 1;
        float v = 0.0f;
        if ((unsigned)h < 56u && (unsigned)ww < 56u)
            v = quant16f(x[(((size_t)n * C_IN + cb * 64 + c) * 56 + h) * 56 + ww]);
        xs[(rr * 64 + c) * 61 + col] = v;
    }
    __syncthreads();

    // transform: thread -> cpair = tid&31 (2 channels), twb = tid>>5
    const int cpair = tid & 31;
    const int twb = tid >> 5;
    for (int g = 0; g < 4; g++) {
        const int tw = twb + g * 8;
        if (tw >= TIL) break;
        float va[2][4][4];
        #pragma unroll
        for (int e = 0; e < 2; e++) {
            const int c = 2 * cpair + e;
            float d[4][4];
            #pragma unroll
            for (int rr = 0; rr < 4; rr++)
                #pragma unroll
                for (int s = 0; s < 4; s++)
                    d[rr][s] = xs[(rr * 64 + c) * 61 + 2 * tw + s];
            float t1[4][4];
            #pragma unroll
            for (int s = 0; s < 4; s++) {
                t1[0][s] = d[0][s] - d[2][s];
                t1[1][s] = d[1][s] + d[2][s];
                t1[2][s] = d[2][s] - d[1][s];
                t1[3][s] = d[1][s] - d[3][s];
            }
            #pragma unroll
            for (int i = 0; i < 4; i++) {
                va[e][i][0] = t1[i][0] - t1[i][2];
                va[e][i][1] = t1[i][1] + t1[i][2];
                va[e][i][2] = t1[i][2] - t1[i][1];
                va[e][i][3] = t1[i][1] - t1[i][3];
            }
        }
        const size_t p2 = (size_t)(n * TIL + th) * TIL + tw;
        #pragma unroll
        for (int i = 0; i < 4; i++)
            #pragma unroll
            for (int j = 0; j < 4; j++)
                *(__half2*)&g_v[(i * 4 + j) * VS2 + p2 * C_IN + cb * 64 + 2 * cpair] =
                    __floats2half2_rn(va[0][i][j], va[1][i][j]);
    }
}

// ---------------- main kernel: 64Mx128N CTA, 8 warps(32x32), occ 1 ----------------
// smem: 4 stages x (A 8KB + B 16KB) = 96KB at [0,98304); Ys 128KB at [98304,229376)
#define A_ST(s) ((s) * 24576u)
#define B_ST(s) ((s) * 24576u + 8192u)
#define YS_OFF  98304u
#define SMEM_TOTAL 229376

__device__ __forceinline__ void cp16(uint32_t dst, const void* src) {
    asm volatile("cp.async.cg.shared.global [%0], [%1], 16;"
                 :: "r"(dst), "l"(src) : "memory");
}

__device__ __forceinline__ void ldsm4(uint32_t* r, uint32_t addr) {
    asm volatile("ldmatrix.sync.aligned.m8n8.x4.shared.b16 {%0,%1,%2,%3}, [%4];"
                 : "=r"(r[0]), "=r"(r[1]), "=r"(r[2]), "=r"(r[3]) : "r"(addr));
}

__device__ __forceinline__ void mma16816(float* c, const uint32_t* a,
                                         uint32_t b0, uint32_t b1) {
    asm volatile(
        "mma.sync.aligned.m16n8k16.row.col.f32.f16.f16.f32 "
        "{%0,%1,%2,%3}, {%4,%5,%6,%7}, {%8,%9}, {%0,%1,%2,%3};"
        : "+f"(c[0]), "+f"(c[1]), "+f"(c[2]), "+f"(c[3])
        : "r"(a[0]), "r"(a[1]), "r"(a[2]), "r"(a[3]), "r"(b0), "r"(b1));
}

__global__ __launch_bounds__(256, 1) void conv_wino2(float* __restrict__ out) {
    extern __shared__ char smem[];
    const uint32_t sb = su32(smem);
    float* ys = (float*)(smem + YS_OFF);       // [128 idx][256 tid]
    const int tid = threadIdx.x;
    const int wid = tid >> 5, lane = tid & 31;
    const int wm = wid & 1, wn = wid >> 1;     // warp tile: 32m x 32n
    const unsigned p0 = blockIdx.x << 6;
    const int n0 = blockIdx.y << 7;

    // A staging: row = tid>>2 (64 rows x 128B), quarter = tid&3 (2 cp16)
    const int rowA = tid >> 2, qA = tid & 3;
    // B staging: row = tid>>1 (128 rows x 128B), half = tid&1 (4 cp16)
    const int rowB = tid >> 1, halfB = tid & 1;

    auto issue = [&](int kc) {
        const int st = kc & 3;
        const int g = kc >> 1;
        const int ch0 = (kc & 1) << 6;
        const int tsel = c_iord[g & 3] * 4 + (g >> 2);   // t = i*4 + j
        const __half* asrc = g_v + (size_t)tsel * VS2
                             + (size_t)(p0 + rowA) * C_IN + ch0 + qA * 16;
        #pragma unroll
        for (int j = 0; j < 2; j++) {
            const uint32_t gg = qA * 2 + j;
            cp16(sb + A_ST(st) + rowA * 128 + ((gg ^ (rowA & 7)) << 4), asrc + j * 8);
        }
        const __half* bsrc = g_u + ((size_t)(tsel * KOUT + n0 + rowB)) * C_IN
                             + ch0 + halfB * 32;
        #pragma unroll
        for (int j = 0; j < 4; j++) {
            const uint32_t gg = halfB * 4 + j;
            cp16(sb + B_ST(st) + rowB * 128 + ((gg ^ (rowB & 7)) << 4), bsrc + j * 8);
        }
        asm volatile("cp.async.commit_group;" ::: "memory");
    };

    // register working sets only (32 floats each); Y lives in smem
    float W0[2][4][4], W1[2][4][4];
    float* wf0 = &W0[0][0][0];
    float* wf1 = &W1[0][0][0];

    auto run2 = [&](int g, float (&acc)[2][4][4]) {
        for (int sub = 0; sub < 2; sub++) {
            const int kc = g * 2 + sub;
            asm volatile("cp.async.wait_group 2;" ::: "memory");
            __syncthreads();
            if (kc + 3 < NCH) issue(kc + 3);
            else asm volatile("cp.async.commit_group;" ::: "memory");

            const uint32_t Ab = sb + A_ST(kc & 3);
            const uint32_t Bb = sb + B_ST(kc & 3);
            #pragma unroll
            for (int stp = 0; stp < 4; stp++) {
                uint32_t ar[2][4], br[2][4];
                #pragma unroll
                for (int mt = 0; mt < 2; mt++) {
                    const int row = wm * 32 + mt * 16 + (lane & 7) + ((lane >> 3) & 1) * 8;
                    const int grp = 2 * stp + (lane >> 4);
                    ldsm4(ar[mt], Ab + row * 128 + ((grp ^ (row & 7)) << 4));
                }
                #pragma unroll
                for (int bt = 0; bt < 2; bt++) {
                    const int row = wn * 32 + bt * 16 + (lane & 7) + (lane >> 4) * 8;
                    const int grp = 2 * stp + ((lane >> 3) & 1);
                    ldsm4(br[bt], Bb + row * 128 + ((grp ^ (row & 7)) << 4));
                }
                #pragma unroll
                for (int mt = 0; mt < 2; mt++)
                    #pragma unroll
                    for (int nt = 0; nt < 4; nt++)
                        mma16816(acc[mt][nt], ar[mt],
                                 br[nt >> 1][(nt & 1) * 2], br[nt >> 1][(nt & 1) * 2 + 1]);
            }
        }
    };

    issue(0); issue(1); issue(2);

    for (int jj = 0; jj < 4; jj++) {
        #pragma unroll
        for (int q = 0; q < 32; q++) wf0[q] = 0.f;

        run2(jj * 4 + 0, W0);            // i=1: W0 = m1j
        #pragma unroll
        for (int q = 0; q < 32; q++) wf1[q] = wf0[q];
        run2(jj * 4 + 1, W0);            // i=2: W0 = m1j + m2j
        #pragma unroll
        for (int q = 0; q < 32; q++) wf1[q] = 2.0f * wf1[q] - wf0[q];  // m1j - m2j
        run2(jj * 4 + 2, W0);            // i=0: W0 = T0j
        run2(jj * 4 + 3, W1);            // i=3 (U negated): W1 = T1j

        // fold into smem Y: Y0+=s0*T0j, Y1+=s1*T0j, Y2+=s0*T1j, Y3+=s1*T1j
        if (jj == 0) {                   // s0=1, s1=0; first touch = store
            #pragma unroll
            for (int q = 0; q < 32; q++) {
                ys[(0 * 32 + q) * 256 + tid] = wf0[q];
                ys[(1 * 32 + q) * 256 + tid] = 0.f;
                ys[(2 * 32 + q) * 256 + tid] = wf1[q];
                ys[(3 * 32 + q) * 256 + tid] = 0.f;
            }
        } else {
            const float s1 = (jj == 1) ? 1.0f : -1.0f;
            const bool use_s0 = (jj <= 2);
            #pragma unroll
            for (int q = 0; q < 32; q++) {
                if (use_s0) {
                    ys[(0 * 32 + q) * 256 + tid] += wf0[q];
                    ys[(2 * 32 + q) * 256 + tid] += wf1[q];
                }
                ys[(1 * 32 + q) * 256 + tid] += s1 * wf0[q];
                ys[(3 * 32 + q) * 256 + tid] += s1 * wf1[q];
            }
        }
    }

    asm volatile("cp.async.wait_group 0;" ::: "memory");
    __syncthreads();

    // ---- epilogue: 2 passes of 64 k through stage region [64 n][65 m] float4 ----
    float4* eb4 = (float4*)smem;
    #pragma unroll
    for (int p = 0; p < 2; p++) {
        if ((wn >> 1) == p) {
            const int r = lane >> 2, ccol = (lane & 3) * 2;
            #pragma unroll
            for (int mt = 0; mt < 2; mt++)
                #pragma unroll
                for (int nt = 0; nt < 4; nt++) {
                    const int m = wm * 32 + mt * 16 + r;
                    const int nl = (wn & 1) * 32 + nt * 8 + ccol;
                    const int fb = mt * 16 + nt * 4;
                    #pragma unroll
                    for (int f = 0; f < 4; f++) {
                        const float4 v = make_float4(
                            ys[(0 * 32 + fb + f) * 256 + tid],
                            ys[(1 * 32 + fb + f) * 256 + tid],
                            ys[(2 * 32 + fb + f) * 256 + tid],
                            ys[(3 * 32 + fb + f) * 256 + tid]);
                        eb4[(nl + (f & 1)) * 65 + m + (f >> 1) * 8] = v;
                    }
                }
        }
        __syncthreads();
        #pragma unroll
        for (int it = 0; it < 16; it++) {
            const int flat = tid + it * 256;
            const int k = flat >> 6;
            const int m = flat & 63;
            const float4 v = eb4[k * 65 + m];
            const unsigned pp = p0 + m;
            const unsigned ni = pp / (TIL * TIL);
            const unsigned rr = pp - ni * (TIL * TIL);
            const unsigned th = rr / TIL;
            const unsigned tw = rr - th * TIL;
            float* o = out + ((size_t)(ni * KOUT + n0 + p * 64 + k) * 56 + 2 * th) * 56
                       + 2 * tw;
            *(float2*)o        = make_float2(v.x, v.y);
            *(float2*)(o + 56) = make_float2(v.z, v.w);
        }
        __syncthreads();
    }
}

extern "C" void kernel_launch(void* const* d_in, const int* in_sizes, int n_in,
                              void* d_out, int out_size) {
    const float* x = (const float*)d_in[0];
    const float* w = (const float*)d_in[1];
    float* out = (float*)d_out;

    cudaFuncSetAttribute(prep_all, cudaFuncAttributeMaxDynamicSharedMemorySize,
                         PREP_SMEM);
    cudaFuncSetAttribute(conv_wino2, cudaFuncAttributeMaxDynamicSharedMemorySize,
                         SMEM_TOTAL);

    prep_all<<<NBLK_V + 128, 256, PREP_SMEM>>>(x, w);
    dim3 grid(PT2 / 64, KOUT / 128);
    conv_wino2<<<grid, 256, SMEM_TOTAL>>>(out);
}

// round 16
// speedup vs baseline: 1.1115x; 1.1115x over previous
#include <cuda_runtime.h>
#include <cuda_fp16.h>
#include <cstdint>

#define H_IN 56
#define W_IN 56
#define C_IN 128
#define KOUT 256
#define NIMG 32
#define W2   28                      // output-pair columns
#define P2TOT (NIMG*H_IN*W2)         // 50176 GEMM rows
#define P2IMG (H_IN*W2)              // 1568
#define VSTRIDE ((size_t)P2TOT*C_IN) // per-t V plane
#define NCHUNK 24                    // 4 GEMMs x 3 r x 2 c-halves, K=64 each

// Winograd-transformed scratch
__device__ __align__(128) __half g_v[4 * VSTRIDE];            // [t][p2][c]
__device__ __align__(128) __half g_u[4 * 3 * KOUT * C_IN];    // [t][r][k][c]

__constant__ int c_ord[4] = {1, 2, 0, 3};   // GEMM processing order -> t

__device__ __forceinline__ float quant16f(float v) {
    float r = rintf(v * 4096.0f);
    r = fminf(fmaxf(r, -32768.0f), 32767.0f);
    return r * (1.0f / 4096.0f);
}

__device__ __forceinline__ uint32_t su32(const void* p) {
    uint32_t a;
    asm("{ .reg .u64 t; cvta.to.shared.u64 t, %1; cvt.u32.u64 %0, t; }"
        : "=r"(a) : "l"(p));
    return a;
}

// ---------------- merged pre-kernel ----------------
// V: blocks [0, 3584): b -> (cb = b&1 [64-ch half], h = (b>>1)%56, n = (b>>1)/56)
// U: blocks [3584, 3584+1536): 256 elems each
#define NBLK_V 3584
#define NBLK_W 1536

__global__ void prep_all(const float* __restrict__ x, const float* __restrict__ w) {
    const int b = blockIdx.x;
    const int tid = threadIdx.x;

    if (b >= NBLK_V) {
        // ---- U transform: [t][r][k][c]; t=3 negated ----
        int idx = (b - NBLK_V) * 256 + tid;
        int t = idx / (3 * KOUT * C_IN);
        int r = (idx / (KOUT * C_IN)) % 3;
        int k = (idx >> 7) & 255;
        int c = idx & 127;
        const float* gp = w + (size_t)k * 1152 + c * 9 + r * 3;
        float g0 = quant16f(gp[0]), g1 = quant16f(gp[1]), g2 = quant16f(gp[2]);
        float u;
        if (t == 0) u = g0;
        else if (t == 1) u = 0.5f * (g0 + g1 + g2);
        else if (t == 2) u = 0.5f * (g0 - g1 + g2);
        else u = -g2;
        g_u[((size_t)((t * 3 + r) * KOUT + k)) * C_IN + c] = __float2half(u);
        return;
    }

    // ---- V transform: one (n, h) row, one 64-channel half ----
    __shared__ __half xs[64][61];    // [c][w+1], w=-1..56; stride 61 (coprime w/ 32)
    const int cb = b & 1;
    const int rh = b >> 1;
    const int h = rh % 56;
    const int n = rh / 56;

    for (int i = tid; i < 64 * W_IN; i += 256) {
        int c = i / W_IN, ww = i - c * W_IN;
        xs[c][ww + 1] = __float2half(
            quant16f(x[(((size_t)n * C_IN + cb * 64 + c) * H_IN + h) * W_IN + ww]));
    }
    if (tid < 64) { xs[tid][0] = __float2half(0.f); xs[tid][57] = __float2half(0.f); }
    __syncthreads();

    const size_t pbase = ((size_t)(n * H_IN + h) * W2) * C_IN;
    for (int j = tid; j < W2 * 32; j += 256) {
        int cp = (j & 31) * 2, w2 = j >> 5;
        float d0a = __half2float(xs[cp][2 * w2]);
        float d1a = __half2float(xs[cp][2 * w2 + 1]);
        float d2a = __half2float(xs[cp][2 * w2 + 2]);
        float d3a = __half2float(xs[cp][2 * w2 + 3]);
        float d0b = __half2float(xs[cp + 1][2 * w2]);
        float d1b = __half2float(xs[cp + 1][2 * w2 + 1]);
        float d2b = __half2float(xs[cp + 1][2 * w2 + 2]);
        float d3b = __half2float(xs[cp + 1][2 * w2 + 3]);
        size_t o = pbase + (size_t)w2 * C_IN + cb * 64 + cp;
        *(__half2*)&g_v[o]               = __floats2half2_rn(d0a - d2a, d0b - d2b);
        *(__half2*)&g_v[VSTRIDE + o]     = __floats2half2_rn(d1a + d2a, d1b + d2b);
        *(__half2*)&g_v[2 * VSTRIDE + o] = __floats2half2_rn(d2a - d1a, d2b - d1b);
        *(__half2*)&g_v[3 * VSTRIDE + o] = __floats2half2_rn(d1a - d3a, d1b - d3b);
    }
}

// ---------------- main kernel (unchanged 189.4µs engine) ----------------
// smem: 4 stages x (A 16KB [128 p2 x 128B] + B 16KB [128 k x 128B])
#define A_ST(s) ((s) * 16384u)
#define B_ST(s) (65536u + (s) * 16384u)
#define SMEM_TOTAL 131072

__device__ __forceinline__ void cp16(uint32_t dst, const void* src, uint32_t ssz) {
    asm volatile("cp.async.cg.shared.global [%0], [%1], 16, %2;"
                 :: "r"(dst), "l"(src), "r"(ssz) : "memory");
}

__device__ __forceinline__ void ldsm4(uint32_t* r, uint32_t addr) {
    asm volatile("ldmatrix.sync.aligned.m8n8.x4.shared.b16 {%0,%1,%2,%3}, [%4];"
                 : "=r"(r[0]), "=r"(r[1]), "=r"(r[2]), "=r"(r[3]) : "r"(addr));
}

__device__ __forceinline__ void mma16816(float* c, const uint32_t* a,
                                         uint32_t b0, uint32_t b1) {
    asm volatile(
        "mma.sync.aligned.m16n8k16.row.col.f32.f16.f16.f32 "
        "{%0,%1,%2,%3}, {%4,%5,%6,%7}, {%8,%9}, {%0,%1,%2,%3};"
        : "+f"(c[0]), "+f"(c[1]), "+f"(c[2]), "+f"(c[3])
        : "r"(a[0]), "r"(a[1]), "r"(a[2]), "r"(a[3]), "r"(b0), "r"(b1));
}

__global__ __launch_bounds__(256, 1) void conv_wino(float* __restrict__ out) {
    extern __shared__ char smem[];
    const uint32_t sb = su32(smem);
    const int tid = threadIdx.x;
    const int wid = tid >> 5, lane = tid & 31;
    const int wm = wid & 1, wn = wid >> 1;       // warp tile: 64m x 32n
    const unsigned p0 = blockIdx.x << 7;
    const int n0 = blockIdx.y << 7;

    // staging coords: row = tid>>1 (128 rows x 128B), 64B half = tid&1
    const int rowT = tid >> 1, half = tid & 1;
    const unsigned p2 = p0 + rowT;
    const unsigned nImg = p2 / P2IMG;
    const unsigned rem = p2 - nImg * P2IMG;
    const int ho = (int)(rem / W2);

    auto issue = [&](int kc) {
        const int st = kc & 3;
        const int gg = kc / 6;
        const int sub = kc - 6 * gg;
        const int r = sub >> 1;
        const int ch0 = (sub & 1) << 6;
        const int tsel = c_ord[gg];
        // A: V_t at input row hi = ho + r - 1 (zero-fill OOB)
        const int hi = ho + r - 1;
        const bool valid = (unsigned)hi < H_IN;
        const size_t arow = valid ? (size_t)p2 + (size_t)(r - 1) * W2 : (size_t)p2;
        const uint32_t ssz = valid ? 16u : 0u;
        const __half* asrc = g_v + (size_t)tsel * VSTRIDE + arow * C_IN
                             + ch0 + half * 32;
        // B: U_t[r][n0+rowT][ch0..]
        const __half* bsrc = g_u + ((size_t)((tsel * 3 + r) * KOUT + n0 + rowT)) * C_IN
                             + ch0 + half * 32;
        #pragma unroll
        for (int j = 0; j < 4; j++) {
            const uint32_t g = half * 4 + j;
            const uint32_t sw = (g ^ (rowT & 7)) << 4;
            cp16(sb + A_ST(st) + rowT * 128 + sw, asrc + j * 8, ssz);
            cp16(sb + B_ST(st) + rowT * 128 + sw, bsrc + j * 8, 16u);
        }
        asm volatile("cp.async.commit_group;" ::: "memory");
    };

    float y0[4][4][4], y1[4][4][4];
    #pragma unroll
    for (int a = 0; a < 4; a++)
        #pragma unroll
        for (int b = 0; b < 4; b++)
            #pragma unroll
            for (int c = 0; c < 4; c++) { y0[a][b][c] = 0.f; y1[a][b][c] = 0.f; }

    auto run6 = [&](int gbase, float (&acc)[4][4][4]) {
        for (int sub = 0; sub < 6; sub++) {
            const int kc = gbase * 6 + sub;
            asm volatile("cp.async.wait_group 2;" ::: "memory");
            __syncthreads();
            if (kc + 3 < NCHUNK) issue(kc + 3);
            else asm volatile("cp.async.commit_group;" ::: "memory");

            const uint32_t Ab = sb + A_ST(kc & 3);
            const uint32_t Bb = sb + B_ST(kc & 3);
            #pragma unroll
            for (int stp = 0; stp < 4; stp++) {
                uint32_t ar[4][4], br[2][4];
                #pragma unroll
                for (int mt = 0; mt < 4; mt++) {
                    const int row = wm * 64 + mt * 16 + (lane & 7) + ((lane >> 3) & 1) * 8;
                    const int grp = 2 * stp + (lane >> 4);
                    ldsm4(ar[mt], Ab + row * 128 + ((grp ^ (row & 7)) << 4));
                }
                #pragma unroll
                for (int bt = 0; bt < 2; bt++) {
                    const int row = wn * 32 + bt * 16 + (lane & 7) + (lane >> 4) * 8;
                    const int grp = 2 * stp + ((lane >> 3) & 1);
                    ldsm4(br[bt], Bb + row * 128 + ((grp ^ (row & 7)) << 4));
                }
                #pragma unroll
                for (int mt = 0; mt < 4; mt++)
                    #pragma unroll
                    for (int nt = 0; nt < 4; nt++)
                        mma16816(acc[mt][nt], ar[mt],
                                 br[nt >> 1][(nt & 1) * 2], br[nt >> 1][(nt & 1) * 2 + 1]);
            }
            // single sync per chunk: next iteration's top sync covers the
            // stage-reuse hazard; trailing sync removed.
        }
    };

    issue(0); issue(1); issue(2);

    run6(0, y0);                    // t=1: y0 = m1
    #pragma unroll
    for (int a = 0; a < 4; a++)
        #pragma unroll
        for (int b = 0; b < 4; b++)
            #pragma unroll
            for (int c = 0; c < 4; c++) y1[a][b][c] = y0[a][b][c];   // y1 = m1
    run6(1, y0);                    // t=2: y0 = m1 + m2
    #pragma unroll
    for (int a = 0; a < 4; a++)
        #pragma unroll
        for (int b = 0; b < 4; b++)
            #pragma unroll
            for (int c = 0; c < 4; c++)
                y1[a][b][c] = 2.0f * y1[a][b][c] - y0[a][b][c];      // y1 = m1 - m2
    run6(2, y0);                    // t=0: y0 = m0 + m1 + m2
    run6(3, y1);                    // t=3 (negated U): y1 = m1 - m2 - m3

    asm volatile("cp.async.wait_group 0;" ::: "memory");
    __syncthreads();

    // ---- epilogue: two 64-channel passes through smem float2 buffer ----
    float2* eb2 = (float2*)smem;
    #pragma unroll
    for (int pass = 0; pass < 2; pass++) {
        if ((wn >> 1) == pass) {
            const int rr = lane >> 2, cc = (lane & 3) * 2;
            #pragma unroll
            for (int mt = 0; mt < 4; mt++)
                #pragma unroll
                for (int nt = 0; nt < 4; nt++) {
                    const int m = wm * 64 + mt * 16 + rr;
                    const int n = (wn & 1) * 32 + nt * 8 + cc;
                    eb2[n * 130 + m]           = make_float2(y0[mt][nt][0], y1[mt][nt][0]);
                    eb2[(n + 1) * 130 + m]     = make_float2(y0[mt][nt][1], y1[mt][nt][1]);
                    eb2[n * 130 + m + 8]       = make_float2(y0[mt][nt][2], y1[mt][nt][2]);
                    eb2[(n + 1) * 130 + m + 8] = make_float2(y0[mt][nt][3], y1[mt][nt][3]);
                }
        }
        __syncthreads();
        for (int j = tid; j < 64 * 128; j += 256) {
            const int k = j >> 7;
            const int m = j & 127;
            const unsigned pp = p0 + m;
            const unsigned ni = pp / P2IMG;
            const unsigned rr = pp - ni * P2IMG;
            const unsigned hh = rr / W2;
            const unsigned w2 = rr - hh * W2;
            *(float2*)(out + ((size_t)(ni * KOUT + n0 + pass * 64 + k) * H_IN + hh)
                       * W_IN + 2 * w2) = eb2[k * 130 + m];
        }
        __syncthreads();
    }
}

extern "C" void kernel_launch(void* const* d_in, const int* in_sizes, int n_in,
                              void* d_out, int out_size) {
    const float* x = (const float*)d_in[0];
    const float* w = (const float*)d_in[1];
    float* out = (float*)d_out;

    cudaFuncSetAttribute(conv_wino, cudaFuncAttributeMaxDynamicSharedMemorySize,
                         SMEM_TOTAL);

    prep_all<<<NBLK_V + NBLK_W, 256>>>(x, w);
    dim3 grid(P2TOT / 128, KOUT / 128);
    conv_wino<<<grid, 256, SMEM_TOTAL>>>(out);
}

// round 17
// speedup vs baseline: 1.1364x; 1.0224x over previous
#include <cuda_runtime.h>
#include <cuda_fp16.h>
#include <cstdint>

#define H_IN 56
#define W_IN 56
#define C_IN 128
#define KOUT 256
#define NIMG 32
#define W2   28                      // output-pair columns
#define P2TOT (NIMG*H_IN*W2)         // 50176 GEMM rows
#define P2IMG (H_IN*W2)              // 1568
#define VSTRIDE ((size_t)P2TOT*C_IN) // per-t V plane
#define NCHUNK 24                    // 4 GEMMs x 3 r x 2 c-halves, K=64 each
#define NTILES 1568                  // 784 m-tiles x 2 n-tiles
#define NPERS  592                   // persistent CTAs = 148 SMs x 2 x 2

// Winograd-transformed scratch
__device__ __align__(128) __half g_v[4 * VSTRIDE];            // [t][p2][c]
__device__ __align__(128) __half g_u[4 * 3 * KOUT * C_IN];    // [t][r][k][c]
__device__ unsigned g_ticket;

__constant__ int c_ord[4] = {1, 2, 0, 3};   // GEMM processing order -> t

__device__ __forceinline__ float quant16f(float v) {
    float r = rintf(v * 4096.0f);
    r = fminf(fmaxf(r, -32768.0f), 32767.0f);
    return r * (1.0f / 4096.0f);
}

__device__ __forceinline__ uint32_t su32(const void* p) {
    uint32_t a;
    asm("{ .reg .u64 t; cvta.to.shared.u64 t, %1; cvt.u32.u64 %0, t; }"
        : "=r"(a) : "l"(p));
    return a;
}

// ---------------- merged pre-kernel (R12 version) ----------------
#define NBLK_X 1792
#define NBLK_W 1536

__global__ void prep_all(const float* __restrict__ x, const float* __restrict__ w) {
    const int b = blockIdx.x;
    const int tid = threadIdx.x;
    if (b == 0 && tid == 0) g_ticket = 0;   // reset ticket for conv launch

    if (b >= NBLK_X) {
        int idx = (b - NBLK_X) * 256 + tid;
        int t = idx / (3 * KOUT * C_IN);
        int r = (idx / (KOUT * C_IN)) % 3;
        int k = (idx >> 7) & 255;
        int c = idx & 127;
        const float* gp = w + (size_t)k * 1152 + c * 9 + r * 3;
        float g0 = quant16f(gp[0]), g1 = quant16f(gp[1]), g2 = quant16f(gp[2]);
        float u;
        if (t == 0) u = g0;
        else if (t == 1) u = 0.5f * (g0 + g1 + g2);
        else if (t == 2) u = 0.5f * (g0 - g1 + g2);
        else u = -g2;
        g_u[((size_t)((t * 3 + r) * KOUT + k)) * C_IN + c] = __float2half(u);
        return;
    }

    __shared__ __half xs[C_IN][58];
    const int h = b % 56;
    const int n = b / 56;

    for (int i = tid; i < C_IN * W_IN; i += 256) {
        int c = i / W_IN, ww = i - c * W_IN;
        xs[c][ww + 1] = __float2half(
            quant16f(x[(((size_t)n * C_IN + c) * H_IN + h) * W_IN + ww]));
    }
    if (tid < C_IN) { xs[tid][0] = __float2half(0.f); xs[tid][57] = __float2half(0.f); }
    __syncthreads();

    const size_t pbase = ((size_t)(n * H_IN + h) * W2) * C_IN;
    for (int j = tid; j < W2 * (C_IN / 2); j += 256) {
        int cp = (j & 63) * 2, w2 = j >> 6;
        float d0a = __half2float(xs[cp][2 * w2]);
        float d1a = __half2float(xs[cp][2 * w2 + 1]);
        float d2a = __half2float(xs[cp][2 * w2 + 2]);
        float d3a = __half2float(xs[cp][2 * w2 + 3]);
        float d0b = __half2float(xs[cp + 1][2 * w2]);
        float d1b = __half2float(xs[cp + 1][2 * w2 + 1]);
        float d2b = __half2float(xs[cp + 1][2 * w2 + 2]);
        float d3b = __half2float(xs[cp + 1][2 * w2 + 3]);
        size_t o = pbase + (size_t)w2 * C_IN + cp;
        *(__half2*)&g_v[o]               = __floats2half2_rn(d0a - d2a, d0b - d2b);
        *(__half2*)&g_v[VSTRIDE + o]     = __floats2half2_rn(d1a + d2a, d1b + d2b);
        *(__half2*)&g_v[2 * VSTRIDE + o] = __floats2half2_rn(d2a - d1a, d2b - d1b);
        *(__half2*)&g_v[3 * VSTRIDE + o] = __floats2half2_rn(d1a - d3a, d1b - d3b);
    }
}

// ---------------- main kernel: R12 engine, persistent + dynamic tickets ----------------
// smem: 4 stages x (A 8KB [64 p2 x 128B] + B 16KB [128 k x 128B]) = 96KB
#define A_ST(s) ((s) * 24576u)
#define B_ST(s) ((s) * 24576u + 8192u)
#define SMEM_TOTAL 98304

__device__ __forceinline__ void cp16(uint32_t dst, const void* src, uint32_t ssz) {
    asm volatile("cp.async.cg.shared.global [%0], [%1], 16, %2;"
                 :: "r"(dst), "l"(src), "r"(ssz) : "memory");
}

__device__ __forceinline__ void ldsm4(uint32_t* r, uint32_t addr) {
    asm volatile("ldmatrix.sync.aligned.m8n8.x4.shared.b16 {%0,%1,%2,%3}, [%4];"
                 : "=r"(r[0]), "=r"(r[1]), "=r"(r[2]), "=r"(r[3]) : "r"(addr));
}

__device__ __forceinline__ void mma16816(float* c, const uint32_t* a,
                                         uint32_t b0, uint32_t b1) {
    asm volatile(
        "mma.sync.aligned.m16n8k16.row.col.f32.f16.f16.f32 "
        "{%0,%1,%2,%3}, {%4,%5,%6,%7}, {%8,%9}, {%0,%1,%2,%3};"
        : "+f"(c[0]), "+f"(c[1]), "+f"(c[2]), "+f"(c[3])
        : "r"(a[0]), "r"(a[1]), "r"(a[2]), "r"(a[3]), "r"(b0), "r"(b1));
}

__global__ __launch_bounds__(256, 2) void conv_wino(float* __restrict__ out) {
    extern __shared__ char smem[];
    const uint32_t sb = su32(smem);
    __shared__ unsigned s_tile;
    const int tid = threadIdx.x;
    const int wid = tid >> 5, lane = tid & 31;
    const int wm = wid & 1, wn = wid >> 1;       // warp tile: 32m x 32n
    // A staging: row = tid>>2 (64 rows x 128B), quarter = tid&3 (2 cp16)
    const int rowA = tid >> 2, qA = tid & 3;
    // B staging: row = tid>>1 (128 rows x 128B), half = tid&1 (4 cp16)
    const int rowB = tid >> 1, halfB = tid & 1;

    for (;;) {
        if (tid == 0) s_tile = atomicAdd(&g_ticket, 1u);
        __syncthreads();
        const unsigned tile = s_tile;
        __syncthreads();
        if (tile >= NTILES) break;

        const unsigned p0 = (tile >> 1) << 6;
        const int n0 = (tile & 1) << 7;

        const unsigned p2 = p0 + rowA;
        const unsigned nImg = p2 / P2IMG;
        const unsigned rem = p2 - nImg * P2IMG;
        const int ho = (int)(rem / W2);

        auto issue = [&](int kc) {
            const int st = kc & 3;
            const int gg = kc / 6;
            const int sub = kc - 6 * gg;
            const int r = sub >> 1;
            const int ch0 = (sub & 1) << 6;
            const int tsel = c_ord[gg];
            const int hi = ho + r - 1;
            const bool valid = (unsigned)hi < H_IN;
            const size_t arow = valid ? (size_t)p2 + (size_t)(r - 1) * W2 : (size_t)p2;
            const uint32_t ssz = valid ? 16u : 0u;
            const __half* asrc = g_v + (size_t)tsel * VSTRIDE + arow * C_IN
                                 + ch0 + qA * 16;
            #pragma unroll
            for (int j = 0; j < 2; j++) {
                const uint32_t g = qA * 2 + j;
                const uint32_t sw = (g ^ (rowA & 7)) << 4;
                cp16(sb + A_ST(st) + rowA * 128 + sw, asrc + j * 8, ssz);
            }
            const __half* bsrc = g_u + ((size_t)((tsel * 3 + r) * KOUT + n0 + rowB))
                                 * C_IN + ch0 + halfB * 32;
            #pragma unroll
            for (int j = 0; j < 4; j++) {
                const uint32_t g = halfB * 4 + j;
                const uint32_t sw = (g ^ (rowB & 7)) << 4;
                cp16(sb + B_ST(st) + rowB * 128 + sw, bsrc + j * 8, 16u);
            }
            asm volatile("cp.async.commit_group;" ::: "memory");
        };

        float y0[2][4][4], y1[2][4][4];
        #pragma unroll
        for (int a = 0; a < 2; a++)
            #pragma unroll
            for (int b = 0; b < 4; b++)
                #pragma unroll
                for (int c = 0; c < 4; c++) { y0[a][b][c] = 0.f; y1[a][b][c] = 0.f; }

        auto run6 = [&](int gbase, float (&acc)[2][4][4]) {
            for (int sub = 0; sub < 6; sub++) {
                const int kc = gbase * 6 + sub;
                asm volatile("cp.async.wait_group 2;" ::: "memory");
                __syncthreads();
                if (kc + 3 < NCHUNK) issue(kc + 3);
                else asm volatile("cp.async.commit_group;" ::: "memory");

                const uint32_t Ab = sb + A_ST(kc & 3);
                const uint32_t Bb = sb + B_ST(kc & 3);
                #pragma unroll
                for (int stp = 0; stp < 4; stp++) {
                    uint32_t ar[2][4], br[2][4];
                    #pragma unroll
                    for (int mt = 0; mt < 2; mt++) {
                        const int row = wm * 32 + mt * 16 + (lane & 7)
                                        + ((lane >> 3) & 1) * 8;
                        const int grp = 2 * stp + (lane >> 4);
                        ldsm4(ar[mt], Ab + row * 128 + ((grp ^ (row & 7)) << 4));
                    }
                    #pragma unroll
                    for (int bt = 0; bt < 2; bt++) {
                        const int row = wn * 32 + bt * 16 + (lane & 7) + (lane >> 4) * 8;
                        const int grp = 2 * stp + ((lane >> 3) & 1);
                        ldsm4(br[bt], Bb + row * 128 + ((grp ^ (row & 7)) << 4));
                    }
                    #pragma unroll
                    for (int mt = 0; mt < 2; mt++)
                        #pragma unroll
                        for (int nt = 0; nt < 4; nt++)
                            mma16816(acc[mt][nt], ar[mt],
                                     br[nt >> 1][(nt & 1) * 2],
                                     br[nt >> 1][(nt & 1) * 2 + 1]);
                }
            }
        };

        issue(0); issue(1); issue(2);

        run6(0, y0);                    // t=1: y0 = m1
        #pragma unroll
        for (int a = 0; a < 2; a++)
            #pragma unroll
            for (int b = 0; b < 4; b++)
                #pragma unroll
                for (int c = 0; c < 4; c++) y1[a][b][c] = y0[a][b][c];
        run6(1, y0);                    // t=2: y0 = m1 + m2
        #pragma unroll
        for (int a = 0; a < 2; a++)
            #pragma unroll
            for (int b = 0; b < 4; b++)
                #pragma unroll
                for (int c = 0; c < 4; c++)
                    y1[a][b][c] = 2.0f * y1[a][b][c] - y0[a][b][c];  // m1 - m2
        run6(2, y0);                    // t=0: y0 = m0 + m1 + m2
        run6(3, y1);                    // t=3 (negated U): y1 = m1 - m2 - m3

        asm volatile("cp.async.wait_group 0;" ::: "memory");
        __syncthreads();

        // ---- epilogue: (y0,y1) -> smem float2 [128 n][66] -> coalesced pairs ----
        float2* eb2 = (float2*)smem;
        {
            const int rr = lane >> 2, cc = (lane & 3) * 2;
            #pragma unroll
            for (int mt = 0; mt < 2; mt++)
                #pragma unroll
                for (int nt = 0; nt < 4; nt++) {
                    const int m = wm * 32 + mt * 16 + rr;
                    const int n = wn * 32 + nt * 8 + cc;
                    eb2[n * 66 + m]           = make_float2(y0[mt][nt][0], y1[mt][nt][0]);
                    eb2[(n + 1) * 66 + m]     = make_float2(y0[mt][nt][1], y1[mt][nt][1]);
                    eb2[n * 66 + m + 8]       = make_float2(y0[mt][nt][2], y1[mt][nt][2]);
                    eb2[(n + 1) * 66 + m + 8] = make_float2(y0[mt][nt][3], y1[mt][nt][3]);
                }
        }
        __syncthreads();
        for (int j = tid; j < 128 * 64; j += 256) {
            const int k = j >> 6;
            const int m = j & 63;
            const unsigned pp = p0 + m;
            const unsigned ni = pp / P2IMG;
            const unsigned rr = pp - ni * P2IMG;
            const unsigned hh = rr / W2;
            const unsigned w2 = rr - hh * W2;
            *(float2*)(out + ((size_t)(ni * KOUT + n0 + k) * H_IN + hh) * W_IN + 2 * w2)
                = eb2[k * 66 + m];
        }
        __syncthreads();
    }
}

extern "C" void kernel_launch(void* const* d_in, const int* in_sizes, int n_in,
                              void* d_out, int out_size) {
    const float* x = (const float*)d_in[0];
    const float* w = (const float*)d_in[1];
    float* out = (float*)d_out;

    cudaFuncSetAttribute(conv_wino, cudaFuncAttributeMaxDynamicSharedMemorySize,
                         SMEM_TOTAL);

    prep_all<<<NBLK_X + NBLK_W, 256>>>(x, w);
    conv_wino<<<NPERS, 256, SMEM_TOTAL>>>(out);
}